// round 5
// baseline (speedup 1.0000x reference)
#include <cuda_runtime.h>
#include <math.h>
#include <float.h>

#define NOBJ 16
#define P    4096
#define EPSF 1e-12f
#define THREADS 128
#define RQ 4                       // queries per thread
#define QCHUNK (THREADS * RQ)      // 512 queries per CTA
#define NCHUNK (P / QCHUNK)        // 8 query chunks
#define TILE   (P / 2)             // 2048 targets per CTA (half split)

typedef unsigned long long u64;

__device__ float g_mask[NOBJ];
__device__ float g_pmin0[2 * NOBJ * P];   // partial min over targets[0:2048),  [dir][n][q]
__device__ float g_pmin1[2 * NOBJ * P];   // partial min over targets[2048:4096)

// ---- packed f32x2 helpers ---------------------------------------------------
__device__ __forceinline__ u64 pk2(float lo, float hi) {
    u64 r; asm("mov.b64 %0, {%1, %2};" : "=l"(r) : "f"(lo), "f"(hi)); return r;
}
__device__ __forceinline__ void upk2(u64 v, float& lo, float& hi) {
    asm("mov.b64 {%0, %1}, %2;" : "=f"(lo), "=f"(hi) : "l"(v));
}
__device__ __forceinline__ u64 fma2(u64 a, u64 b, u64 c) {
    u64 d; asm("fma.rn.f32x2 %0, %1, %2, %3;" : "=l"(d) : "l"(a), "l"(b), "l"(c));
    return d;
}

// ---------------------------------------------------------------------------
// Kernel 1: per-object mask over point_set_2; zero the output scalar.
// ---------------------------------------------------------------------------
__global__ void mask_kernel(const float* __restrict__ set2, float* __restrict__ out)
{
    const int n = blockIdx.x;
    const float* base = set2 + (size_t)n * P * 2;

    float s = 0.f;
    for (int i = threadIdx.x; i < P * 2; i += blockDim.x) s += base[i];

    #pragma unroll
    for (int o = 16; o; o >>= 1) s += __shfl_xor_sync(0xFFFFFFFFu, s, o);

    __shared__ float red[8];
    const int w = threadIdx.x >> 5, l = threadIdx.x & 31;
    if (l == 0) red[w] = s;
    __syncthreads();
    if (w == 0) {
        s = (l < (blockDim.x >> 5)) ? red[l] : 0.f;
        #pragma unroll
        for (int o = 16; o; o >>= 1) s += __shfl_xor_sync(0xFFFFFFFFu, s, o);
        if (l == 0) g_mask[n] = (s >= 0.f) ? 1.f : 0.f;
    }
    if (n == 0 && threadIdx.x == 0) *out = 0.f;   // d_out is poisoned
}

// ---------------------------------------------------------------------------
// Kernel 2: partial chamfer min over one half of the target set.
// blockIdx = (chunk, object, dir*2 + half). 128 threads -> all 4 SMSPs busy.
// Writes (min over tile of d^2) per query to g_pmin{half}. No atomics.
// ---------------------------------------------------------------------------
__global__ void __launch_bounds__(THREADS)
chamfer_kernel(const float* __restrict__ set1, const float* __restrict__ set2)
{
    const int chunk = blockIdx.x;
    const int n     = blockIdx.y;
    const int dir   = blockIdx.z >> 1;
    const int half  = blockIdx.z & 1;

    const float* qbase = (dir == 0 ? set1 : set2) + (size_t)n * P * 2;
    const float* tbase = (dir == 0 ? set2 : set1) + (size_t)n * P * 2
                       + (size_t)half * TILE * 2;

    __shared__ __align__(16) float sx[TILE];   // 8 KB
    __shared__ __align__(16) float sy[TILE];   // 8 KB
    __shared__ __align__(16) float ss[TILE];   // 8 KB

    // cooperative stage: 2 points per thread-iter via float4 load
    const float4* tg4 = (const float4*)tbase;  // (x0,y0,x1,y1)
    for (int j = threadIdx.x; j < TILE / 2; j += THREADS) {
        float4 v = tg4[j];
        *(float2*)&sx[2 * j] = make_float2(v.x, v.z);
        *(float2*)&sy[2 * j] = make_float2(v.y, v.w);
        *(float2*)&ss[2 * j] = make_float2(fmaf(v.x, v.x, v.y * v.y),
                                           fmaf(v.z, v.z, v.w * v.w));
    }
    __syncthreads();

    // load RQ queries; duplicate -2x / -2y into packed operands
    u64   mxx[RQ], myy[RQ];
    float s1[RQ], mn[RQ];
    const int q0 = chunk * QCHUNK;
    #pragma unroll
    for (int r = 0; r < RQ; r++) {
        const int q = q0 + r * THREADS + threadIdx.x;
        const float x = qbase[2 * q];
        const float y = qbase[2 * q + 1];
        const float mx = -2.f * x, my = -2.f * y;
        mxx[r] = pk2(mx, mx);
        myy[r] = pk2(my, my);
        s1[r]  = fmaf(x, x, y * y);
        mn[r]  = FLT_MAX;
    }

    const ulonglong2* xp = (const ulonglong2*)sx;   // element j = targets 4j..4j+3
    const ulonglong2* yp = (const ulonglong2*)sy;
    const ulonglong2* sp = (const ulonglong2*)ss;

    #pragma unroll 8
    for (int j = 0; j < TILE / 4; j++) {
        const ulonglong2 X = xp[j];
        const ulonglong2 Y = yp[j];
        const ulonglong2 S = sp[j];
        #pragma unroll
        for (int r = 0; r < RQ; r++) {
            const u64 d01 = fma2(mxx[r], X.x, fma2(myy[r], Y.x, S.x));
            const u64 d23 = fma2(mxx[r], X.y, fma2(myy[r], Y.y, S.y));
            float a, b, c, d;
            upk2(d01, a, b);
            upk2(d23, c, d);
            mn[r] = fminf(mn[r], fminf(fminf(a, b), fminf(c, d)));
        }
    }

    // write partial minima (d^2 = mn + s1), coalesced over threadIdx
    float* pout = (half == 0 ? g_pmin0 : g_pmin1) + ((size_t)dir * NOBJ + n) * P;
    #pragma unroll
    for (int r = 0; r < RQ; r++) {
        const int q = q0 + r * THREADS + threadIdx.x;
        pout[q] = mn[r] + s1[r];
    }
}

// ---------------------------------------------------------------------------
// Kernel 3: finalize — combine halves, clamp, sqrt, masked mean, atomicAdd.
// 2*NOBJ*P = 131072 elements.
// ---------------------------------------------------------------------------
#define FT 256
__global__ void __launch_bounds__(FT)
final_kernel(float* __restrict__ out)
{
    const int total = 2 * NOBJ * P;
    float acc = 0.f;
    for (int i = blockIdx.x * FT + threadIdx.x; i < total; i += gridDim.x * FT) {
        const int n = (i / P) & (NOBJ - 1);
        float d2 = fminf(g_pmin0[i], g_pmin1[i]);
        d2 = fmaxf(d2, EPSF);
        acc += sqrtf(d2) * g_mask[n];
    }

    #pragma unroll
    for (int o = 16; o; o >>= 1) acc += __shfl_xor_sync(0xFFFFFFFFu, acc, o);
    __shared__ float red[FT / 32];
    if ((threadIdx.x & 31) == 0) red[threadIdx.x >> 5] = acc;
    __syncthreads();
    if (threadIdx.x == 0) {
        float tot = 0.f;
        #pragma unroll
        for (int w = 0; w < FT / 32; w++) tot += red[w];
        atomicAdd(out, tot * (0.5f / ((float)NOBJ * (float)P)));
    }
}

// ---------------------------------------------------------------------------
extern "C" void kernel_launch(void* const* d_in, const int* in_sizes, int n_in,
                              void* d_out, int out_size)
{
    const float* set1 = (const float*)d_in[0];
    const float* set2 = (const float*)d_in[1];
    float* out = (float*)d_out;

    mask_kernel<<<NOBJ, 256>>>(set2, out);
    dim3 grid(NCHUNK, NOBJ, 4);                    // 8 x 16 x (2 dir * 2 halves) = 512 CTAs
    chamfer_kernel<<<grid, THREADS>>>(set1, set2);
    final_kernel<<<128, FT>>>(out);
}